// round 5
// baseline (speedup 1.0000x reference)
#include <cuda_runtime.h>

#define B_N   8
#define H_IN  384
#define W_IN  384
#define HO    382
#define WO    382
#define KST   64
#define NB    9
#define HOWO  (HO * WO)

// ---- packed f32x2 helpers (Blackwell) ----
__device__ __forceinline__ unsigned long long dup2(float v) {
    unsigned long long r;
    asm("mov.b64 %0, {%1, %1};" : "=l"(r) : "f"(v));
    return r;
}
__device__ __forceinline__ unsigned long long fma2(unsigned long long a,
                                                   unsigned long long b,
                                                   unsigned long long c) {
    unsigned long long d;
    asm("fma.rn.f32x2 %0, %1, %2, %3;" : "=l"(d) : "l"(a), "l"(b), "l"(c));
    return d;
}
__device__ __forceinline__ unsigned long long mul2(unsigned long long a,
                                                   unsigned long long b) {
    unsigned long long d;
    asm("mul.rn.f32x2 %0, %1, %2;" : "=l"(d) : "l"(a), "l"(b));
    return d;
}
__device__ __forceinline__ unsigned long long add2(unsigned long long a,
                                                   unsigned long long b) {
    unsigned long long d;
    asm("add.rn.f32x2 %0, %1, %2;" : "=l"(d) : "l"(a), "l"(b));
    return d;
}
__device__ __forceinline__ void unpack2(unsigned long long d, float& lo, float& hi) {
    asm("mov.b64 {%0, %1}, %2;" : "=f"(lo), "=f"(hi) : "l"(d));
}

// Block: (48, 4) = 192 threads, 2 CTAs/SM. Thread = 8 consecutive output
// columns of one output row (3x10 input window). Grid: (96 row-groups, 8).
//
// Shared sW: per state-pair sp (32 pairs), stride 24 floats (96 B, 16B-
// aligned -> LDS.128 broadcast):
//   [sp*24 + 0..1]       = (b[2sp], b[2sp+1])
//   [sp*24 + 2+2k..3+2k] = (W[k][2sp], W[k][2sp+1])  k = 0..8
__global__ __launch_bounds__(192, 2) void qconv_kernel(
    const float* __restrict__ x, const float* __restrict__ W,
    const float* __restrict__ b, const int* __restrict__ keys,
    float* __restrict__ out)
{
    __shared__ __align__(16) float sW[32 * 24];   // 3072 B
    __shared__ float sKeys[KST * NB];             // 2304 B

    const float c0 = 1.5707963267948966f; // pi/2

    const int tid = threadIdx.y * 48 + threadIdx.x;

    if (tid < KST) {
        const int s = tid;
        const int sp = s >> 1, h = s & 1;
        sW[sp * 24 + h] = b[s];
        #pragma unroll
        for (int k = 0; k < NB; ++k)
            sW[sp * 24 + 2 + 2 * k + h] = W[k * KST + s];
    }
    for (int idx = tid; idx < KST * NB; idx += 192)
        sKeys[idx] = (float)keys[idx];
    __syncthreads();

    const int bz = blockIdx.y;
    const int i  = blockIdx.x * 4 + threadIdx.y;
    if (i >= HO) return;
    const int j0 = threadIdx.x * 8;       // multiple of 8, <= 376 (32B aligned)

    const float* xb = x + bz * (H_IN * W_IN);

    // 3x10 patch window: float4 + float4 + predicated float2 per row.
    // Transform (v - 0.5f) * pi/2 exactly as the reference; duplicate into
    // both f32x2 lanes (two adjacent Fock states share the patch value).
    unsigned long long P[30];
    const bool tail_ok = (j0 + 9 < W_IN);   // false only for tx == 47
    #pragma unroll
    for (int r = 0; r < 3; ++r) {
        const float* rp = xb + (i + r) * W_IN + j0;
        float4 va = *reinterpret_cast<const float4*>(rp);
        float4 vb = *reinterpret_cast<const float4*>(rp + 4);
        float2 vc = tail_ok ? *reinterpret_cast<const float2*>(rp + 8)
                            : make_float2(0.f, 0.f);
        float v[10] = { va.x, va.y, va.z, va.w, vb.x, vb.y, vb.z, vb.w,
                        vc.x, vc.y };
        #pragma unroll
        for (int c = 0; c < 10; ++c)
            P[r * 10 + c] = dup2((v[c] - 0.5f) * c0);
    }

    float best[8];
    int   bi[8];
    #pragma unroll
    for (int p = 0; p < 8; ++p) { best[p] = -3.4e38f; bi[p] = 0; }

    #pragma unroll 4
    for (int sp = 0; sp < 32; ++sp) {
        const ulonglong2* wp =
            reinterpret_cast<const ulonglong2*>(&sW[sp * 24]);
        const ulonglong2 q0 = wp[0];   // (b_pair, w0)
        const ulonglong2 q1 = wp[1];   // (w1, w2)
        const ulonglong2 q2 = wp[2];   // (w3, w4)
        const ulonglong2 q3 = wp[3];   // (w5, w6)
        const ulonglong2 q4 = wp[4];   // (w7, w8)

        const unsigned long long w[9] =
            { q0.y, q1.x, q1.y, q2.x, q2.y, q3.x, q3.y, q4.x, q4.y };
        // P-offset of weight k within a row-stride-10 window
        const int off[9] = { 0, 1, 2, 10, 11, 12, 20, 21, 22 };

        unsigned long long a[8];
        // Bit-identical summation order: (((p0*w0 + p1*w1) + ... ) + b)
        #pragma unroll
        for (int p = 0; p < 8; ++p)
            a[p] = mul2(P[p], w[0]);
        #pragma unroll
        for (int k = 1; k < NB; ++k) {
            #pragma unroll
            for (int p = 0; p < 8; ++p)
                a[p] = fma2(P[off[k] + p], w[k], a[p]);
        }
        #pragma unroll
        for (int p = 0; p < 8; ++p)
            a[p] = add2(a[p], q0.x);

        // Argmax: pair winner first (independent of best), then one
        // best-dependent compare. Identical to sequential strict-> scan.
        const int s0 = sp * 2;
        #pragma unroll
        for (int p = 0; p < 8; ++p) {
            float lo, hi;
            unpack2(a[p], lo, hi);
            const bool q = hi > lo;
            const float cand = q ? hi : lo;
            const int   ci   = q ? s0 + 1 : s0;
            if (cand > best[p]) { best[p] = cand; bi[p] = ci; }
        }
    }

    // Decode + store (float2 stores, 8B-aligned: j0 even).
    // Pair pp covers pixels j0+2pp, j0+2pp+1; tx==47 has 6 valid pixels
    // (WO - 376 = 6, even), so validity is per-pair.
    const int obase = bz * (NB * HOWO) + i * WO + j0;
    #pragma unroll
    for (int k = 0; k < NB; ++k) {
        float* op = out + obase + k * HOWO;
        #pragma unroll
        for (int pp = 0; pp < 4; ++pp) {
            if (j0 + 2 * pp + 1 < WO) {
                *reinterpret_cast<float2*>(op + 2 * pp) =
                    make_float2(sKeys[bi[2 * pp] * NB + k],
                                sKeys[bi[2 * pp + 1] * NB + k]);
            }
        }
    }
}

extern "C" void kernel_launch(void* const* d_in, const int* in_sizes, int n_in,
                              void* d_out, int out_size) {
    const float* x    = (const float*)d_in[0];
    const float* W    = (const float*)d_in[1];
    const float* b    = (const float*)d_in[2];
    const int*   keys = (const int*)d_in[3];
    float*       out  = (float*)d_out;

    dim3 block(48, 4);            // 192 threads, 6 warps
    dim3 grid((HO + 3) / 4, B_N); // (96, 8)
    qconv_kernel<<<grid, block>>>(x, W, b, keys, out);
}

// round 6
// speedup vs baseline: 1.1823x; 1.1823x over previous
#include <cuda_runtime.h>

#define B_N   8
#define H_IN  384
#define W_IN  384
#define HO    382
#define WO    382
#define KST   64
#define NB    9
#define HOWO  (HO * WO)

// ---- packed f32x2 helpers (Blackwell) ----
__device__ __forceinline__ unsigned long long dup2(float v) {
    unsigned long long r;
    asm("mov.b64 %0, {%1, %1};" : "=l"(r) : "f"(v));
    return r;
}
__device__ __forceinline__ unsigned long long fma2(unsigned long long a,
                                                   unsigned long long b,
                                                   unsigned long long c) {
    unsigned long long d;
    asm("fma.rn.f32x2 %0, %1, %2, %3;" : "=l"(d) : "l"(a), "l"(b), "l"(c));
    return d;
}
__device__ __forceinline__ unsigned long long mul2(unsigned long long a,
                                                   unsigned long long b) {
    unsigned long long d;
    asm("mul.rn.f32x2 %0, %1, %2;" : "=l"(d) : "l"(a), "l"(b));
    return d;
}
__device__ __forceinline__ unsigned long long add2(unsigned long long a,
                                                   unsigned long long b) {
    unsigned long long d;
    asm("add.rn.f32x2 %0, %1, %2;" : "=l"(d) : "l"(a), "l"(b));
    return d;
}
__device__ __forceinline__ void unpack2(unsigned long long d, float& lo, float& hi) {
    asm("mov.b64 {%0, %1}, %2;" : "=f"(lo), "=f"(hi) : "l"(d));
}

// Block: (32, 4) = 128 threads, <=56 regs -> 9 CTAs/SM resident.
// Thread = 4 consecutive output columns of one output row.
// Grid: (3 col-slabs of 128, 96 row-groups, 8 batches) = 2304 blocks.
//
// Shared sW: per state-pair sp (32 pairs), stride 24 floats (96 B,
// 16B-aligned -> LDS.128 broadcast):
//   [sp*24 + 0..1]       = (b[2sp], b[2sp+1])
//   [sp*24 + 2+2k..3+2k] = (W[k][2sp], W[k][2sp+1])  k = 0..8
__global__ __launch_bounds__(128, 9) void qconv_kernel(
    const float* __restrict__ x, const float* __restrict__ W,
    const float* __restrict__ b, const int* __restrict__ keys,
    float* __restrict__ out)
{
    __shared__ __align__(16) float sW[32 * 24];   // 3072 B
    __shared__ float sKeys[KST * NB];             // 2304 B

    const float c0 = 1.5707963267948966f; // pi/2

    const int tid = threadIdx.y * 32 + threadIdx.x;

    if (tid < KST) {
        const int s = tid;
        const int sp = s >> 1, h = s & 1;
        sW[sp * 24 + h] = b[s];
        #pragma unroll
        for (int k = 0; k < NB; ++k)
            sW[sp * 24 + 2 + 2 * k + h] = W[k * KST + s];
    }
    for (int idx = tid; idx < KST * NB; idx += 128)
        sKeys[idx] = (float)keys[idx];
    __syncthreads();

    const int bz = blockIdx.z;
    const int i  = blockIdx.y * 4 + threadIdx.y;
    if (i >= HO) return;
    const int j0 = blockIdx.x * 128 + threadIdx.x * 4;  // multiple of 4, <= 380

    const float* xb = x + bz * (H_IN * W_IN);

    // 3x6 patch block: float4 + predicated float2 per row; transform
    // (v - 0.5f) * pi/2 exactly as the reference; duplicate into f32x2 lanes.
    unsigned long long P[18];
    const bool tail_ok = (j0 <= W_IN - 6);   // false only for j0 == 380
    #pragma unroll
    for (int r = 0; r < 3; ++r) {
        const float* rp = xb + (i + r) * W_IN + j0;
        float4 v4 = *reinterpret_cast<const float4*>(rp);
        float2 v2 = tail_ok ? *reinterpret_cast<const float2*>(rp + 4)
                            : make_float2(0.f, 0.f);
        float v[6] = { v4.x, v4.y, v4.z, v4.w, v2.x, v2.y };
        #pragma unroll
        for (int c = 0; c < 6; ++c)
            P[r * 6 + c] = dup2((v[c] - 0.5f) * c0);
    }

    float best0 = -3.4e38f, best1 = -3.4e38f, best2 = -3.4e38f, best3 = -3.4e38f;
    int   bi0 = 0, bi1 = 0, bi2 = 0, bi3 = 0;

    #pragma unroll 16
    for (int sp = 0; sp < 32; ++sp) {
        const ulonglong2* wp =
            reinterpret_cast<const ulonglong2*>(&sW[sp * 24]);
        const ulonglong2 q0 = wp[0];   // (b_pair, w0)
        const ulonglong2 q1 = wp[1];   // (w1, w2)
        const ulonglong2 q2 = wp[2];   // (w3, w4)
        const ulonglong2 q3 = wp[3];   // (w5, w6)
        const ulonglong2 q4 = wp[4];   // (w7, w8)

        // Bit-identical summation order: (((p0*w0 + p1*w1) + ... ) + b)
        unsigned long long a0 = mul2(P[0], q0.y);
        unsigned long long a1 = mul2(P[1], q0.y);
        unsigned long long a2 = mul2(P[2], q0.y);
        unsigned long long a3 = mul2(P[3], q0.y);

        a0 = fma2(P[1],  q1.x, a0);  a1 = fma2(P[2],  q1.x, a1);
        a2 = fma2(P[3],  q1.x, a2);  a3 = fma2(P[4],  q1.x, a3);

        a0 = fma2(P[2],  q1.y, a0);  a1 = fma2(P[3],  q1.y, a1);
        a2 = fma2(P[4],  q1.y, a2);  a3 = fma2(P[5],  q1.y, a3);

        a0 = fma2(P[6],  q2.x, a0);  a1 = fma2(P[7],  q2.x, a1);
        a2 = fma2(P[8],  q2.x, a2);  a3 = fma2(P[9],  q2.x, a3);

        a0 = fma2(P[7],  q2.y, a0);  a1 = fma2(P[8],  q2.y, a1);
        a2 = fma2(P[9],  q2.y, a2);  a3 = fma2(P[10], q2.y, a3);

        a0 = fma2(P[8],  q3.x, a0);  a1 = fma2(P[9],  q3.x, a1);
        a2 = fma2(P[10], q3.x, a2);  a3 = fma2(P[11], q3.x, a3);

        a0 = fma2(P[12], q3.y, a0);  a1 = fma2(P[13], q3.y, a1);
        a2 = fma2(P[14], q3.y, a2);  a3 = fma2(P[15], q3.y, a3);

        a0 = fma2(P[13], q4.x, a0);  a1 = fma2(P[14], q4.x, a1);
        a2 = fma2(P[15], q4.x, a2);  a3 = fma2(P[16], q4.x, a3);

        a0 = fma2(P[14], q4.y, a0);  a1 = fma2(P[15], q4.y, a1);
        a2 = fma2(P[16], q4.y, a2);  a3 = fma2(P[17], q4.y, a3);

        a0 = add2(a0, q0.x);
        a1 = add2(a1, q0.x);
        a2 = add2(a2, q0.x);
        a3 = add2(a3, q0.x);

        // Argmax: pair winner first (independent of best), then one
        // best-dependent compare. Identical to sequential strict-> scan.
        const int s0 = sp * 2;
        float lo, hi;
        {
            unpack2(a0, lo, hi);
            const bool q = hi > lo;
            const float cand = q ? hi : lo;
            const int   ci   = q ? s0 + 1 : s0;
            if (cand > best0) { best0 = cand; bi0 = ci; }
        }
        {
            unpack2(a1, lo, hi);
            const bool q = hi > lo;
            const float cand = q ? hi : lo;
            const int   ci   = q ? s0 + 1 : s0;
            if (cand > best1) { best1 = cand; bi1 = ci; }
        }
        {
            unpack2(a2, lo, hi);
            const bool q = hi > lo;
            const float cand = q ? hi : lo;
            const int   ci   = q ? s0 + 1 : s0;
            if (cand > best2) { best2 = cand; bi2 = ci; }
        }
        {
            unpack2(a3, lo, hi);
            const bool q = hi > lo;
            const float cand = q ? hi : lo;
            const int   ci   = q ? s0 + 1 : s0;
            if (cand > best3) { best3 = cand; bi3 = ci; }
        }
    }

    // Decode + store (int32 addressing; float2 stores, 8B-aligned).
    const int obase = bz * (NB * HOWO) + i * WO + j0;
    const float* kr0 = &sKeys[bi0 * NB];
    const float* kr1 = &sKeys[bi1 * NB];
    const float* kr2 = &sKeys[bi2 * NB];
    const float* kr3 = &sKeys[bi3 * NB];
    const bool hi_ok = (j0 + 3 < WO);
    #pragma unroll
    for (int k = 0; k < NB; ++k) {
        float* op = out + obase + k * HOWO;
        *reinterpret_cast<float2*>(op) = make_float2(kr0[k], kr1[k]);
        if (hi_ok)
            *reinterpret_cast<float2*>(op + 2) = make_float2(kr2[k], kr3[k]);
    }
}

extern "C" void kernel_launch(void* const* d_in, const int* in_sizes, int n_in,
                              void* d_out, int out_size) {
    const float* x    = (const float*)d_in[0];
    const float* W    = (const float*)d_in[1];
    const float* b    = (const float*)d_in[2];
    const int*   keys = (const int*)d_in[3];
    float*       out  = (float*)d_out;

    dim3 block(32, 4);                 // 128 threads
    dim3 grid(3, (HO + 3) / 4, B_N);   // (3, 96, 8) = 2304 blocks
    qconv_kernel<<<grid, block>>>(x, W, b, keys, out);
}